// round 14
// baseline (speedup 1.0000x reference)
#include <cuda_runtime.h>
#include <cuda_fp16.h>
#include <math.h>
#include <stdint.h>

#define TOK   2048
#define HD    1024
#define NHEAD 16
#define DH    64
#define NEXP  8
#define FF    4096
#define SEQ   1024

// ---------------- scratch ----------------
__device__ __half g_h1h[TOK * HD];
__device__ __half g_qh[TOK * HD];
__device__ __half g_kh[TOK * HD];
__device__ __half g_vh[TOK * HD];
__device__ __half g_attnh[TOK * HD];
__device__ float  g_x1[TOK * HD];
__device__ float  g_h2[TOK * HD];
__device__ __half g_h2h[TOK * HD];
__device__ float  g_we[TOK * NEXP];
__device__ float  g_usage[NEXP];
__device__ int    g_cnt[NEXP];
__device__ int    g_idx[NEXP * TOK];
__device__ __half g_hgA[(size_t)NEXP * TOK * FF];
__device__ __half g_hgB[(size_t)NEXP * TOK * FF];
// fp16 weights
__device__ __half g_wqh[HD * HD];
__device__ __half g_wkh[HD * HD];
__device__ __half g_wvh[HD * HD];
__device__ __half g_woh[HD * HD];
__device__ __half g_w1h[(size_t)NEXP * FF * HD];
__device__ __half g_w2h[(size_t)NEXP * HD * FF];
__device__ __half g_w3h[(size_t)NEXP * FF * HD];

// ---------------- helpers ----------------
__device__ __forceinline__ uint32_t smem_u32(const void* p) {
    uint32_t a;
    asm("{ .reg .u64 t; cvta.to.shared.u64 t, %1; cvt.u32.u64 %0, t; }" : "=r"(a) : "l"(p));
    return a;
}
__device__ __forceinline__ void mma16(float* c, uint32_t a0, uint32_t a1, uint32_t a2,
                                      uint32_t a3, uint32_t b0, uint32_t b1) {
    asm volatile(
        "mma.sync.aligned.m16n8k16.row.col.f32.f16.f16.f32 "
        "{%0,%1,%2,%3}, {%4,%5,%6,%7}, {%8,%9}, {%0,%1,%2,%3};"
        : "+f"(c[0]), "+f"(c[1]), "+f"(c[2]), "+f"(c[3])
        : "r"(a0), "r"(a1), "r"(a2), "r"(a3), "r"(b0), "r"(b1));
}
__device__ __forceinline__ void cp16(uint32_t dst, const void* src) {
    asm volatile("cp.async.cg.shared.global [%0], [%1], 16;" :: "r"(dst), "l"(src));
}
#define CP_COMMIT() asm volatile("cp.async.commit_group;" ::: "memory")
#define CP_WAIT0()  asm volatile("cp.async.wait_group 0;" ::: "memory")
__device__ __forceinline__ uint32_t pack2(float lo, float hi) {
    __half2 h = __floats2half2_rn(lo, hi);
    return *(uint32_t*)&h;
}

// ---- fp16 GEMM smem: As[2][128][48h] | Bs[2][128][48h] | Aptr[128] ----
#define LDWH 48
#define HSTG 12288
#define HOFF_B 24576
#define HOFF_PTR 49152
#define SMEM_GEMMH 50176

__device__ __forceinline__ void issue_stage_h(uint32_t sb, const __half* const* Aptr,
                                              const __half* Bbase, size_t strideB,
                                              int k0, int s, int tid) {
#pragma unroll
    for (int i = 0; i < 2; i++) {
        int idx = tid + i * 256;
        int row = idx >> 2, ch = idx & 3;
        uint32_t off = (uint32_t)(s * HSTG) + (uint32_t)(row * 96 + ch * 16);
        cp16(sb + off, Aptr[row] + k0 + ch * 8);
        cp16(sb + HOFF_B + off, Bbase + (size_t)row * strideB + k0 + ch * 8);
    }
}

__device__ __forceinline__ void compute_tile_h(const __half* As, const __half* Bs,
                                               int warpM, int warpN, int g, int tg,
                                               float acc[4][4][4]) {
#pragma unroll
    for (int ks = 0; ks < 2; ks++) {
        int kk = ks * 16 + 4 * tg;
        uint2 aL[4], aH[4];
#pragma unroll
        for (int mt = 0; mt < 4; mt++) {
            aL[mt] = *(const uint2*)&As[(warpM + mt * 16 + g    ) * LDWH + kk];
            aH[mt] = *(const uint2*)&As[(warpM + mt * 16 + g + 8) * LDWH + kk];
        }
#pragma unroll
        for (int nt = 0; nt < 4; nt++) {
            uint2 bv = *(const uint2*)&Bs[(warpN + nt * 8 + g) * LDWH + kk];
#pragma unroll
            for (int mt = 0; mt < 4; mt++)
                mma16(acc[mt][nt], aL[mt].x, aH[mt].x, aL[mt].y, aH[mt].y, bv.x, bv.y);
        }
    }
}

// ---------------- init ----------------
__global__ void init_kernel() {
    int t = threadIdx.x;
    if (t < NEXP) { g_cnt[t] = 0; g_usage[t] = 0.f; }
}

// ---------------- fp32 -> fp16 conversions ----------------
__global__ void cvt4_kernel(const float* __restrict__ a, const float* __restrict__ b,
                            const float* __restrict__ c, const float* __restrict__ d,
                            int n4) {
    int i = blockIdx.x * 256 + threadIdx.x;
    if (i >= n4) return;
    const float* src = blockIdx.y == 0 ? a : (blockIdx.y == 1 ? b : (blockIdx.y == 2 ? c : d));
    __half* dst = blockIdx.y == 0 ? g_wqh : (blockIdx.y == 1 ? g_wkh : (blockIdx.y == 2 ? g_wvh : g_woh));
    float4 v = ((const float4*)src)[i];
    ((__half2*)dst)[2 * i]     = __floats2half2_rn(v.x, v.y);
    ((__half2*)dst)[2 * i + 1] = __floats2half2_rn(v.z, v.w);
}
__global__ void cvt3_kernel(const float* __restrict__ a, const float* __restrict__ b,
                            const float* __restrict__ c, int n4) {
    int i = blockIdx.x * 256 + threadIdx.x;
    if (i >= n4) return;
    const float* src = blockIdx.y == 0 ? a : (blockIdx.y == 1 ? b : c);
    __half* dst = blockIdx.y == 0 ? g_w1h : (blockIdx.y == 1 ? g_w2h : g_w3h);
    float4 v = ((const float4*)src)[i];
    ((__half2*)dst)[2 * i]     = __floats2half2_rn(v.x, v.y);
    ((__half2*)dst)[2 * i + 1] = __floats2half2_rn(v.z, v.w);
}

// ---------------- layernorm (fp16 out; optional fp32 out) ----------------
__global__ void ln_kernel(const float* __restrict__ x, const float* __restrict__ g,
                          const float* __restrict__ b, float* __restrict__ y,
                          __half* __restrict__ yh) {
    __shared__ float red[256];
    int row = blockIdx.x;
    const float* xr = x + (size_t)row * HD;
    float s = 0.f;
    for (int i = threadIdx.x; i < HD; i += 256) s += xr[i];
    red[threadIdx.x] = s; __syncthreads();
    for (int o = 128; o > 0; o >>= 1) {
        if (threadIdx.x < o) red[threadIdx.x] += red[threadIdx.x + o];
        __syncthreads();
    }
    float mu = red[0] * (1.f / HD);
    __syncthreads();
    float v = 0.f;
    for (int i = threadIdx.x; i < HD; i += 256) { float d = xr[i] - mu; v += d * d; }
    red[threadIdx.x] = v; __syncthreads();
    for (int o = 128; o > 0; o >>= 1) {
        if (threadIdx.x < o) red[threadIdx.x] += red[threadIdx.x + o];
        __syncthreads();
    }
    float rstd = rsqrtf(red[0] * (1.f / HD) + 1e-5f);
    __half* yhr = yh + (size_t)row * HD;
    for (int i = threadIdx.x; i < HD; i += 256) {
        float val = (xr[i] - mu) * rstd * g[i] + b[i];
        if (y) y[(size_t)row * HD + i] = val;
        yhr[i] = __float2half(val);
    }
}

// ---------------- QKV projections (fp16 in/out) ----------------
__global__ __launch_bounds__(256) void qkv_mma() {
    extern __shared__ char sm[];
    const __half** Aptr = (const __half**)(sm + HOFF_PTR);
    int tid = threadIdx.x, wid = tid >> 5, lane = tid & 31;
    int g = lane >> 2, tg = lane & 3;
    int warpM = (wid >> 2) * 64, warpN = (wid & 3) * 32;
    const __half* W = blockIdx.z == 0 ? g_wqh : (blockIdx.z == 1 ? g_wkh : g_wvh);
    __half* C = blockIdx.z == 0 ? g_qh : (blockIdx.z == 1 ? g_kh : g_vh);
    int rowBase = blockIdx.y * 128, colBase = blockIdx.x * 128;
    if (tid < 128) Aptr[tid] = g_h1h + (size_t)(rowBase + tid) * HD;
    __syncthreads();
    const __half* Bbase = W + (size_t)colBase * HD;
    uint32_t sb = smem_u32(sm);
    float acc[4][4][4] = {};
    issue_stage_h(sb, Aptr, Bbase, HD, 0, 0, tid); CP_COMMIT();
    for (int kb = 0; kb < HD / 32; kb++) {
        CP_WAIT0(); __syncthreads();
        if (kb + 1 < HD / 32) { issue_stage_h(sb, Aptr, Bbase, HD, (kb + 1) * 32, (kb + 1) & 1, tid); CP_COMMIT(); }
        compute_tile_h((const __half*)(sm + (kb & 1) * HSTG),
                       (const __half*)(sm + HOFF_B + (kb & 1) * HSTG),
                       warpM, warpN, g, tg, acc);
        __syncthreads();
    }
#pragma unroll
    for (int mt = 0; mt < 4; mt++)
#pragma unroll
        for (int nt = 0; nt < 4; nt++) {
            int r0 = rowBase + warpM + mt * 16 + g;
            int c0 = colBase + warpN + nt * 8 + 2 * tg;
            *(__half2*)(C + (size_t)r0 * HD + c0) = __floats2half2_rn(acc[mt][nt][0], acc[mt][nt][1]);
            *(__half2*)(C + (size_t)(r0 + 8) * HD + c0) = __floats2half2_rn(acc[mt][nt][2], acc[mt][nt][3]);
        }
}

// ---------------- O projection + residual (writes g_x1 AND out) ----------------
__global__ __launch_bounds__(256) void oproj_mma(const float* __restrict__ xres,
                                                 float* __restrict__ out) {
    extern __shared__ char sm[];
    const __half** Aptr = (const __half**)(sm + HOFF_PTR);
    int tid = threadIdx.x, wid = tid >> 5, lane = tid & 31;
    int g = lane >> 2, tg = lane & 3;
    int warpM = (wid >> 2) * 64, warpN = (wid & 3) * 32;
    int rowBase = blockIdx.y * 128, colBase = blockIdx.x * 128;
    if (tid < 128) Aptr[tid] = g_attnh + (size_t)(rowBase + tid) * HD;
    __syncthreads();
    const __half* Bbase = g_woh + (size_t)colBase * HD;
    uint32_t sb = smem_u32(sm);
    float acc[4][4][4] = {};
    issue_stage_h(sb, Aptr, Bbase, HD, 0, 0, tid); CP_COMMIT();
    for (int kb = 0; kb < HD / 32; kb++) {
        CP_WAIT0(); __syncthreads();
        if (kb + 1 < HD / 32) { issue_stage_h(sb, Aptr, Bbase, HD, (kb + 1) * 32, (kb + 1) & 1, tid); CP_COMMIT(); }
        compute_tile_h((const __half*)(sm + (kb & 1) * HSTG),
                       (const __half*)(sm + HOFF_B + (kb & 1) * HSTG),
                       warpM, warpN, g, tg, acc);
        __syncthreads();
    }
#pragma unroll
    for (int mt = 0; mt < 4; mt++)
#pragma unroll
        for (int nt = 0; nt < 4; nt++) {
            int r0 = rowBase + warpM + mt * 16 + g;
            int c0 = colBase + warpN + nt * 8 + 2 * tg;
            float2 a = *(const float2*)(xres + (size_t)r0 * HD + c0);
            float2 b = *(const float2*)(xres + (size_t)(r0 + 8) * HD + c0);
            float2 v0 = make_float2(acc[mt][nt][0] + a.x, acc[mt][nt][1] + a.y);
            float2 v1 = make_float2(acc[mt][nt][2] + b.x, acc[mt][nt][3] + b.y);
            *(float2*)(g_x1 + (size_t)r0 * HD + c0) = v0;
            *(float2*)(g_x1 + (size_t)(r0 + 8) * HD + c0) = v1;
            *(float2*)(out + (size_t)r0 * HD + c0) = v0;
            *(float2*)(out + (size_t)(r0 + 8) * HD + c0) = v1;
        }
}

// ---------------- flash attention (causal, fp16 mma) ----------------
#define AQR 128
#define QLD 72
#define VLD 72
#define SM_K (128 * QLD)
#define SM_V (192 * QLD)
#define SMEM_ATTN ((192 * QLD + 64 * VLD) * 2)
__global__ __launch_bounds__(256) void attn_mma() {
    extern __shared__ char sm[];
    __half* Qs = (__half*)sm;
    __half* Ks = (__half*)sm + SM_K;
    __half* Vt = (__half*)sm + SM_V;
    int qb = gridDim.x - 1 - blockIdx.x;
    int bh = blockIdx.y;
    int b = bh >> 4, h = bh & 15;
    int tid = threadIdx.x, wid = tid >> 5, lane = tid & 31;
    int g = lane >> 2, tg = lane & 3;
    int qr0 = wid * 16;
    const __half* qbase = g_qh + (size_t)(b * SEQ + qb * AQR) * HD + h * DH;
#pragma unroll
    for (int i = 0; i < 4; i++) {
        int idx = tid + i * 256;
        int row = idx >> 3, c = (idx & 7) * 8;
        *(uint4*)&Qs[row * QLD + c] = *(const uint4*)(qbase + (size_t)row * HD + c);
    }
    float m0 = -1e30f, m1 = -1e30f, l0 = 0.f, l1 = 0.f;
    float o[8][4] = {};
    int nkt = qb * 2 + 2;
    int rmaxWarp = qb * AQR + qr0 + 15;
    for (int kt = 0; kt < nkt; kt++) {
        __syncthreads();
        const __half* kbase = g_kh + (size_t)(b * SEQ + kt * 64) * HD + h * DH;
        const __half* vbase = g_vh + (size_t)(b * SEQ + kt * 64) * HD + h * DH;
#pragma unroll
        for (int i = 0; i < 2; i++) {
            int idx = tid + i * 256;
            int row = idx >> 3, c = (idx & 7) * 8;
            *(uint4*)&Ks[row * QLD + c] = *(const uint4*)(kbase + (size_t)row * HD + c);
        }
#pragma unroll
        for (int i = 0; i < 8; i++) {
            int idx = tid + i * 256;
            int key = idx & 63, c0 = (idx >> 6) * 2;
            __half2 v = *(const __half2*)(vbase + (size_t)key * HD + c0);
            Vt[(c0 + 0) * VLD + key] = __low2half(v);
            Vt[(c0 + 1) * VLD + key] = __high2half(v);
        }
        __syncthreads();
        if (kt * 64 > rmaxWarp) continue;
        float s[8][4] = {};
#pragma unroll
        for (int c = 0; c < 4; c++) {
            int kk = c * 16 + 4 * tg;
            uint2 aLo = *(const uint2*)&Qs[(qr0 + g) * QLD + kk];
            uint2 aHi = *(const uint2*)&Qs[(qr0 + g + 8) * QLD + kk];
#pragma unroll
            for (int nt = 0; nt < 8; nt++) {
                uint2 bv = *(const uint2*)&Ks[(nt * 8 + g) * QLD + kk];
                mma16(s[nt], aLo.x, aHi.x, aLo.y, aHi.y, bv.x, bv.y);
            }
        }
        int r0 = qb * AQR + qr0 + g, r1 = r0 + 8;
#pragma unroll
        for (int nt = 0; nt < 8; nt++) {
            int c = kt * 64 + nt * 8 + 2 * tg;
            s[nt][0] = (c     > r0) ? -1e30f : s[nt][0] * 0.125f;
            s[nt][1] = (c + 1 > r0) ? -1e30f : s[nt][1] * 0.125f;
            s[nt][2] = (c     > r1) ? -1e30f : s[nt][2] * 0.125f;
            s[nt][3] = (c + 1 > r1) ? -1e30f : s[nt][3] * 0.125f;
        }
        float mx0 = -1e30f, mx1 = -1e30f;
#pragma unroll
        for (int nt = 0; nt < 8; nt++) {
            mx0 = fmaxf(mx0, fmaxf(s[nt][0], s[nt][1]));
            mx1 = fmaxf(mx1, fmaxf(s[nt][2], s[nt][3]));
        }
        mx0 = fmaxf(mx0, __shfl_xor_sync(0xffffffffu, mx0, 1));
        mx0 = fmaxf(mx0, __shfl_xor_sync(0xffffffffu, mx0, 2));
        mx1 = fmaxf(mx1, __shfl_xor_sync(0xffffffffu, mx1, 1));
        mx1 = fmaxf(mx1, __shfl_xor_sync(0xffffffffu, mx1, 2));
        float mn0 = fmaxf(m0, mx0), mn1 = fmaxf(m1, mx1);
        float rs0 = 0.f, rs1 = 0.f;
#pragma unroll
        for (int nt = 0; nt < 8; nt++) {
            s[nt][0] = __expf(s[nt][0] - mn0); rs0 += s[nt][0];
            s[nt][1] = __expf(s[nt][1] - mn0); rs0 += s[nt][1];
            s[nt][2] = __expf(s[nt][2] - mn1); rs1 += s[nt][2];
            s[nt][3] = __expf(s[nt][3] - mn1); rs1 += s[nt][3];
        }
        rs0 += __shfl_xor_sync(0xffffffffu, rs0, 1);
        rs0 += __shfl_xor_sync(0xffffffffu, rs0, 2);
        rs1 += __shfl_xor_sync(0xffffffffu, rs1, 1);
        rs1 += __shfl_xor_sync(0xffffffffu, rs1, 2);
        float al0 = __expf(m0 - mn0), al1 = __expf(m1 - mn1);
        m0 = mn0; m1 = mn1;
        l0 = l0 * al0 + rs0; l1 = l1 * al1 + rs1;
#pragma unroll
        for (int nt = 0; nt < 8; nt++) {
            o[nt][0] *= al0; o[nt][1] *= al0;
            o[nt][2] *= al1; o[nt][3] *= al1;
        }
#pragma unroll
        for (int j = 0; j < 4; j++) {
            uint32_t a0 = pack2(s[2 * j][0], s[2 * j][1]);
            uint32_t a1 = pack2(s[2 * j][2], s[2 * j][3]);
            uint32_t a2 = pack2(s[2 * j + 1][0], s[2 * j + 1][1]);
            uint32_t a3 = pack2(s[2 * j + 1][2], s[2 * j + 1][3]);
            int kbase2 = j * 16 + 2 * tg;
#pragma unroll
            for (int nt = 0; nt < 8; nt++) {
                const __half* vp = &Vt[(nt * 8 + g) * VLD];
                uint32_t b0 = *(const uint32_t*)(vp + kbase2);
                uint32_t b1 = *(const uint32_t*)(vp + kbase2 + 8);
                mma16(o[nt], a0, a1, a2, a3, b0, b1);
            }
        }
    }
    float i0 = 1.f / l0, i1 = 1.f / l1;
    __half* obase = g_attnh + (size_t)(b * SEQ + qb * AQR + qr0) * HD + h * DH;
#pragma unroll
    for (int nt = 0; nt < 8; nt++) {
        int c = nt * 8 + 2 * tg;
        *(__half2*)(obase + (size_t)g * HD + c)       = __floats2half2_rn(o[nt][0] * i0, o[nt][1] * i0);
        *(__half2*)(obase + (size_t)(g + 8) * HD + c) = __floats2half2_rn(o[nt][2] * i1, o[nt][3] * i1);
    }
}

// ---------------- router (fp32 logits) ----------------
__global__ void router_kernel(const float* __restrict__ Wr) {
    int gwarp = (blockIdx.x * blockDim.x + threadIdx.x) >> 5;
    int lane = threadIdx.x & 31;
    if (gwarp >= TOK) return;
    const float* xr = g_h2 + (size_t)gwarp * HD;
    float acc[NEXP] = {};
    for (int i = lane; i < HD; i += 32) {
        float xv = xr[i];
#pragma unroll
        for (int e = 0; e < NEXP; e++) acc[e] += xv * Wr[e * HD + i];
    }
#pragma unroll
    for (int e = 0; e < NEXP; e++)
#pragma unroll
        for (int o = 16; o > 0; o >>= 1)
            acc[e] += __shfl_xor_sync(0xffffffffu, acc[e], o);
    if (lane == 0) {
        float mx = acc[0];
#pragma unroll
        for (int e = 1; e < NEXP; e++) mx = fmaxf(mx, acc[e]);
        float p[NEXP], se = 0.f;
#pragma unroll
        for (int e = 0; e < NEXP; e++) { p[e] = __expf(acc[e] - mx); se += p[e]; }
        float inv = 1.f / (se * (float)TOK);
#pragma unroll
        for (int e = 0; e < NEXP; e++) atomicAdd(&g_usage[e], p[e] * inv);
        int i0 = 0;
#pragma unroll
        for (int e = 1; e < NEXP; e++) if (acc[e] > acc[i0]) i0 = e;
        int i1 = (i0 == 0) ? 1 : 0;
#pragma unroll
        for (int e = 0; e < NEXP; e++) if (e != i0 && acc[e] > acc[i1]) i1 = e;
        float l0 = acc[i0], l1 = acc[i1];
        float m2 = fmaxf(l0, l1);
        float e0 = __expf(l0 - m2), e1 = __expf(l1 - m2);
        float s2 = e0 + e1;
        g_we[gwarp * NEXP + i0] = e0 / s2;
        g_we[gwarp * NEXP + i1] = e1 / s2;
        int p0 = atomicAdd(&g_cnt[i0], 1); g_idx[i0 * TOK + p0] = gwarp;
        int p1 = atomicAdd(&g_cnt[i1], 1); g_idx[i1 * TOK + p1] = gwarp;
    }
}

// ---------------- MoE up (fp16) ----------------
__global__ __launch_bounds__(256) void moe_up_mma() {
    extern __shared__ char sm[];
    int e = blockIdx.z;
    int cnt = g_cnt[e];
    int rowBase = blockIdx.y * 128;
    if (rowBase >= cnt) return;
    int half_ = blockIdx.x >> 5;
    int colBase = (blockIdx.x & 31) * 128;
    const __half* W = half_ ? g_w3h : g_w1h;
    __half* dstb = half_ ? g_hgB : g_hgA;
    const __half** Aptr = (const __half**)(sm + HOFF_PTR);
    int tid = threadIdx.x, wid = tid >> 5, lane = tid & 31;
    int g = lane >> 2, tg = lane & 3;
    int warpM = (wid >> 2) * 64, warpN = (wid & 3) * 32;
    if (tid < 128) {
        int p = rowBase + tid;
        Aptr[tid] = g_h2h + (size_t)g_idx[e * TOK + (p < cnt ? p : cnt - 1)] * HD;
    }
    __syncthreads();
    const __half* Bbase = W + (size_t)e * FF * HD + (size_t)colBase * HD;
    uint32_t sb = smem_u32(sm);
    float acc[4][4][4] = {};
    issue_stage_h(sb, Aptr, Bbase, HD, 0, 0, tid); CP_COMMIT();
    for (int kb = 0; kb < HD / 32; kb++) {
        CP_WAIT0(); __syncthreads();
        if (kb + 1 < HD / 32) { issue_stage_h(sb, Aptr, Bbase, HD, (kb + 1) * 32, (kb + 1) & 1, tid); CP_COMMIT(); }
        compute_tile_h((const __half*)(sm + (kb & 1) * HSTG),
                       (const __half*)(sm + HOFF_B + (kb & 1) * HSTG),
                       warpM, warpN, g, tg, acc);
        __syncthreads();
    }
#pragma unroll
    for (int mt = 0; mt < 4; mt++)
#pragma unroll
        for (int nt = 0; nt < 4; nt++) {
            int p0 = rowBase + warpM + mt * 16 + g;
            int c0 = colBase + warpN + nt * 8 + 2 * tg;
            if (p0 < cnt)
                *(__half2*)(dstb + ((size_t)e * TOK + p0) * FF + c0) =
                    __floats2half2_rn(acc[mt][nt][0], acc[mt][nt][1]);
            if (p0 + 8 < cnt)
                *(__half2*)(dstb + ((size_t)e * TOK + p0 + 8) * FF + c0) =
                    __floats2half2_rn(acc[mt][nt][2], acc[mt][nt][3]);
        }
}

// ---------------- silu * mul (half) ----------------
__global__ void silu_mul_kernel() {
    int e = blockIdx.y;
    int cnt = g_cnt[e];
    int pos = blockIdx.x;
    if (pos >= cnt) return;
    size_t off2 = ((size_t)e * TOK + pos) * (FF / 2);
    __half2* A2 = (__half2*)g_hgA;
    const __half2* B2 = (const __half2*)g_hgB;
    for (int i = threadIdx.x; i < FF / 2; i += 256) {
        float2 a = __half22float2(A2[off2 + i]);
        float2 b = __half22float2(B2[off2 + i]);
        a.x = a.x / (1.f + __expf(-a.x)) * b.x;
        a.y = a.y / (1.f + __expf(-a.y)) * b.y;
        A2[off2 + i] = __floats2half2_rn(a.x, a.y);
    }
}

// ---------------- MoE down (fp16, scatter-atomic) ----------------
__global__ __launch_bounds__(256) void moe_down_mma(float* __restrict__ out) {
    extern __shared__ char sm[];
    int e = blockIdx.z;
    int cnt = g_cnt[e];
    int rowBase = blockIdx.y * 128;
    if (rowBase >= cnt) return;
    int colBase = blockIdx.x * 128;
    const __half** Aptr = (const __half**)(sm + HOFF_PTR);
    int tid = threadIdx.x, wid = tid >> 5, lane = tid & 31;
    int g = lane >> 2, tg = lane & 3;
    int warpM = (wid >> 2) * 64, warpN = (wid & 3) * 32;
    if (tid < 128)
        Aptr[tid] = g_hgA + ((size_t)e * TOK + rowBase + tid) * FF;
    __syncthreads();
    const __half* Bbase = g_w2h + (size_t)e * HD * FF + (size_t)colBase * FF;
    uint32_t sb = smem_u32(sm);
    float acc[4][4][4] = {};
    issue_stage_h(sb, Aptr, Bbase, FF, 0, 0, tid); CP_COMMIT();
    for (int kb = 0; kb < FF / 32; kb++) {
        CP_WAIT0(); __syncthreads();
        if (kb + 1 < FF / 32) { issue_stage_h(sb, Aptr, Bbase, FF, (kb + 1) * 32, (kb + 1) & 1, tid); CP_COMMIT(); }
        compute_tile_h((const __half*)(sm + (kb & 1) * HSTG),
                       (const __half*)(sm + HOFF_B + (kb & 1) * HSTG),
                       warpM, warpN, g, tg, acc);
        __syncthreads();
    }
#pragma unroll
    for (int mt = 0; mt < 4; mt++) {
        int p0 = rowBase + warpM + mt * 16 + g;
        int p1 = p0 + 8;
        int t0 = 0, t1 = 0; float w0 = 0.f, w1 = 0.f;
        if (p0 < cnt) { t0 = g_idx[e * TOK + p0]; w0 = g_we[t0 * NEXP + e]; }
        if (p1 < cnt) { t1 = g_idx[e * TOK + p1]; w1 = g_we[t1 * NEXP + e]; }
#pragma unroll
        for (int nt = 0; nt < 4; nt++) {
            int c0 = colBase + warpN + nt * 8 + 2 * tg;
            if (p0 < cnt) {
                atomicAdd(out + (size_t)t0 * HD + c0,     w0 * acc[mt][nt][0]);
                atomicAdd(out + (size_t)t0 * HD + c0 + 1, w0 * acc[mt][nt][1]);
            }
            if (p1 < cnt) {
                atomicAdd(out + (size_t)t1 * HD + c0,     w1 * acc[mt][nt][2]);
                atomicAdd(out + (size_t)t1 * HD + c0 + 1, w1 * acc[mt][nt][3]);
            }
        }
    }
}

// ---------------- lb ----------------
__global__ void lb_kernel(float* __restrict__ out) {
    if (threadIdx.x == 0) {
        float s = 0.f;
#pragma unroll
        for (int e = 0; e < NEXP; e++) s += g_usage[e] * g_usage[e];
        out[(size_t)TOK * HD] = (float)NEXP * s;
    }
}

// ---------------- launch ----------------
extern "C" void kernel_launch(void* const* d_in, const int* in_sizes, int n_in,
                              void* d_out, int out_size) {
    const float* x    = (const float*)d_in[0];
    const float* Wq   = (const float*)d_in[1];
    const float* Wk   = (const float*)d_in[2];
    const float* Wv   = (const float*)d_in[3];
    const float* Wo   = (const float*)d_in[4];
    const float* ln1g = (const float*)d_in[5];
    const float* ln1b = (const float*)d_in[6];
    const float* ln2g = (const float*)d_in[7];
    const float* ln2b = (const float*)d_in[8];
    const float* Wr   = (const float*)d_in[9];
    const float* W1   = (const float*)d_in[10];
    const float* W2   = (const float*)d_in[11];
    const float* W3   = (const float*)d_in[12];
    float* out = (float*)d_out;

    float *px1, *ph2;
    __half *ph1h, *ph2h;
    cudaGetSymbolAddress((void**)&ph1h, g_h1h);
    cudaGetSymbolAddress((void**)&px1,  g_x1);
    cudaGetSymbolAddress((void**)&ph2,  g_h2);
    cudaGetSymbolAddress((void**)&ph2h, g_h2h);

    cudaFuncSetAttribute(qkv_mma,      cudaFuncAttributeMaxDynamicSharedMemorySize, SMEM_GEMMH);
    cudaFuncSetAttribute(oproj_mma,    cudaFuncAttributeMaxDynamicSharedMemorySize, SMEM_GEMMH);
    cudaFuncSetAttribute(moe_up_mma,   cudaFuncAttributeMaxDynamicSharedMemorySize, SMEM_GEMMH);
    cudaFuncSetAttribute(moe_down_mma, cudaFuncAttributeMaxDynamicSharedMemorySize, SMEM_GEMMH);
    cudaFuncSetAttribute(attn_mma,     cudaFuncAttributeMaxDynamicSharedMemorySize, SMEM_ATTN);

    // side stream + fork/join events (created per call, never destroyed:
    // kernel_launch runs only a couple of times; avoids mid-capture destroys)
    cudaStream_t s2;
    cudaEvent_t evFork, evJoin;
    cudaStreamCreateWithFlags(&s2, cudaStreamNonBlocking);
    cudaEventCreateWithFlags(&evFork, cudaEventDisableTiming);
    cudaEventCreateWithFlags(&evJoin, cudaEventDisableTiming);

    const int NQ4 = HD * HD / 4;
    const int NW4 = NEXP * FF * HD / 4;

    // fork: big weight conversion runs concurrently with attention phase
    cudaEventRecord(evFork, 0);
    cudaStreamWaitEvent(s2, evFork, 0);
    cvt3_kernel<<<dim3((NW4 + 255) / 256, 3), 256, 0, s2>>>(W1, W2, W3, NW4);
    cudaEventRecord(evJoin, s2);

    init_kernel<<<1, 32>>>();
    cvt4_kernel<<<dim3((NQ4 + 255) / 256, 4), 256>>>(Wq, Wk, Wv, Wo, NQ4);
    ln_kernel<<<TOK, 256>>>(x, ln1g, ln1b, nullptr, ph1h);
    qkv_mma<<<dim3(HD / 128, TOK / 128, 3), 256, SMEM_GEMMH>>>();
    attn_mma<<<dim3(SEQ / AQR, 2 * NHEAD), 256, SMEM_ATTN>>>();
    oproj_mma<<<dim3(HD / 128, TOK / 128), 256, SMEM_GEMMH>>>(x, out);
    ln_kernel<<<TOK, 256>>>(px1, ln2g, ln2b, ph2, ph2h);
    router_kernel<<<TOK / 8, 256>>>(Wr);

    // join: MoE needs the converted expert weights
    cudaStreamWaitEvent(0, evJoin, 0);
    moe_up_mma<<<dim3(2 * FF / 128, TOK / 128, NEXP), 256, SMEM_GEMMH>>>();
    silu_mul_kernel<<<dim3(TOK, NEXP), 256>>>();
    moe_down_mma<<<dim3(HD / 128, TOK / 128, NEXP), 256, SMEM_GEMMH>>>(out);
    if ((long long)out_size >= (long long)TOK * HD + 1)
        lb_kernel<<<1, 32>>>(out);
}

// round 17
// speedup vs baseline: 1.0393x; 1.0393x over previous
#include <cuda_runtime.h>
#include <cuda_fp16.h>
#include <math.h>
#include <stdint.h>

#define TOK   2048
#define HD    1024
#define NHEAD 16
#define DH    64
#define NEXP  8
#define FF    4096
#define SEQ   1024

// ---------------- scratch ----------------
__device__ __half g_h1h[TOK * HD];
__device__ __half g_qh[TOK * HD];
__device__ __half g_kh[TOK * HD];
__device__ __half g_vh[TOK * HD];
__device__ __half g_attnh[TOK * HD];
__device__ float  g_h2[TOK * HD];
__device__ __half g_h2h[TOK * HD];
__device__ float  g_we[TOK * NEXP];
__device__ float  g_usage[NEXP];
__device__ int    g_cnt[NEXP];
__device__ int    g_idx[NEXP * TOK];
__device__ __half g_hgA[(size_t)NEXP * TOK * FF];
__device__ __half g_hgB[(size_t)NEXP * TOK * FF];
// fp16 weights
__device__ __half g_wqh[HD * HD];
__device__ __half g_wkh[HD * HD];
__device__ __half g_wvh[HD * HD];
__device__ __half g_woh[HD * HD];
__device__ __half g_w1h[(size_t)NEXP * FF * HD];
__device__ __half g_w2h[(size_t)NEXP * HD * FF];
__device__ __half g_w3h[(size_t)NEXP * FF * HD];

// ---------------- helpers ----------------
__device__ __forceinline__ uint32_t smem_u32(const void* p) {
    uint32_t a;
    asm("{ .reg .u64 t; cvta.to.shared.u64 t, %1; cvt.u32.u64 %0, t; }" : "=r"(a) : "l"(p));
    return a;
}
__device__ __forceinline__ void mma16(float* c, uint32_t a0, uint32_t a1, uint32_t a2,
                                      uint32_t a3, uint32_t b0, uint32_t b1) {
    asm volatile(
        "mma.sync.aligned.m16n8k16.row.col.f32.f16.f16.f32 "
        "{%0,%1,%2,%3}, {%4,%5,%6,%7}, {%8,%9}, {%0,%1,%2,%3};"
        : "+f"(c[0]), "+f"(c[1]), "+f"(c[2]), "+f"(c[3])
        : "r"(a0), "r"(a1), "r"(a2), "r"(a3), "r"(b0), "r"(b1));
}
__device__ __forceinline__ void cp16(uint32_t dst, const void* src) {
    asm volatile("cp.async.cg.shared.global [%0], [%1], 16;" :: "r"(dst), "l"(src));
}
#define CP_COMMIT() asm volatile("cp.async.commit_group;" ::: "memory")
#define CP_WAIT1()  asm volatile("cp.async.wait_group 1;" ::: "memory")
__device__ __forceinline__ uint32_t pack2(float lo, float hi) {
    __half2 h = __floats2half2_rn(lo, hi);
    return *(uint32_t*)&h;
}

// ---- fp16 GEMM smem (3-stage): As[3][128][48h] | Bs[3][128][48h] | Aptr[128] ----
#define LDWH 48
#define HSTG 12288                 // bytes per stage per matrix (128*96)
#define HOFF_B 36864               // 3*HSTG
#define HOFF_PTR 73728             // 6*HSTG
#define SMEM_GEMMH 74752

__device__ __forceinline__ void issue_stage_h(uint32_t sb, const __half* const* Aptr,
                                              const __half* Bbase, size_t strideB,
                                              int k0, int s, int tid) {
#pragma unroll
    for (int i = 0; i < 2; i++) {
        int idx = tid + i * 256;
        int row = idx >> 2, ch = idx & 3;
        uint32_t off = (uint32_t)(s * HSTG) + (uint32_t)(row * 96 + ch * 16);
        cp16(sb + off, Aptr[row] + k0 + ch * 8);
        cp16(sb + HOFF_B + off, Bbase + (size_t)row * strideB + k0 + ch * 8);
    }
}

__device__ __forceinline__ void compute_tile_h(const __half* As, const __half* Bs,
                                               int warpM, int warpN, int g, int tg,
                                               float acc[4][4][4]) {
#pragma unroll
    for (int ks = 0; ks < 2; ks++) {
        int kk = ks * 16 + 4 * tg;
        uint2 aL[4], aH[4];
#pragma unroll
        for (int mt = 0; mt < 4; mt++) {
            aL[mt] = *(const uint2*)&As[(warpM + mt * 16 + g    ) * LDWH + kk];
            aH[mt] = *(const uint2*)&As[(warpM + mt * 16 + g + 8) * LDWH + kk];
        }
#pragma unroll
        for (int nt = 0; nt < 4; nt++) {
            uint2 bv = *(const uint2*)&Bs[(warpN + nt * 8 + g) * LDWH + kk];
#pragma unroll
            for (int mt = 0; mt < 4; mt++)
                mma16(acc[mt][nt], aL[mt].x, aH[mt].x, aL[mt].y, aH[mt].y, bv.x, bv.y);
        }
    }
}

// 3-stage mainloop shared by all GEMMs (one __syncthreads per k-block)
#define GEMM_MAINLOOP(CH, STRIDE)                                                   \
    issue_stage_h(sb, Aptr, Bbase, STRIDE, 0, 0, tid); CP_COMMIT();                 \
    issue_stage_h(sb, Aptr, Bbase, STRIDE, 32, 1, tid); CP_COMMIT();                \
    {                                                                               \
        int s2i = 2;                                                                \
        for (int kb = 0; kb < (CH); kb++) {                                         \
            CP_WAIT1(); __syncthreads();                                            \
            if (kb + 2 < (CH)) {                                                    \
                issue_stage_h(sb, Aptr, Bbase, STRIDE, (kb + 2) * 32, s2i, tid);    \
                s2i = s2i == 2 ? 0 : s2i + 1;                                       \
            }                                                                       \
            CP_COMMIT();                                                            \
            int bi = kb % 3;                                                        \
            compute_tile_h((const __half*)(sm + bi * HSTG),                         \
                           (const __half*)(sm + HOFF_B + bi * HSTG),                \
                           warpM, warpN, g, tg, acc);                               \
        }                                                                           \
    }

// ---------------- init ----------------
__global__ void init_kernel() {
    int t = threadIdx.x;
    if (t < NEXP) { g_cnt[t] = 0; g_usage[t] = 0.f; }
}

// ---------------- fp32 -> fp16 conversions ----------------
__global__ void cvt4_kernel(const float* __restrict__ a, const float* __restrict__ b,
                            const float* __restrict__ c, const float* __restrict__ d,
                            int n4) {
    int i = blockIdx.x * 256 + threadIdx.x;
    if (i >= n4) return;
    const float* src = blockIdx.y == 0 ? a : (blockIdx.y == 1 ? b : (blockIdx.y == 2 ? c : d));
    __half* dst = blockIdx.y == 0 ? g_wqh : (blockIdx.y == 1 ? g_wkh : (blockIdx.y == 2 ? g_wvh : g_woh));
    float4 v = ((const float4*)src)[i];
    ((__half2*)dst)[2 * i]     = __floats2half2_rn(v.x, v.y);
    ((__half2*)dst)[2 * i + 1] = __floats2half2_rn(v.z, v.w);
}
__global__ void cvt3_kernel(const float* __restrict__ a, const float* __restrict__ b,
                            const float* __restrict__ c, int n4) {
    int i = blockIdx.x * 256 + threadIdx.x;
    if (i >= n4) return;
    const float* src = blockIdx.y == 0 ? a : (blockIdx.y == 1 ? b : c);
    __half* dst = blockIdx.y == 0 ? g_w1h : (blockIdx.y == 1 ? g_w2h : g_w3h);
    float4 v = ((const float4*)src)[i];
    ((__half2*)dst)[2 * i]     = __floats2half2_rn(v.x, v.y);
    ((__half2*)dst)[2 * i + 1] = __floats2half2_rn(v.z, v.w);
}

// ---------------- layernorm (fp16 out; optional fp32 out) ----------------
__global__ void ln_kernel(const float* __restrict__ x, const float* __restrict__ g,
                          const float* __restrict__ b, float* __restrict__ y,
                          __half* __restrict__ yh) {
    __shared__ float red[256];
    int row = blockIdx.x;
    const float* xr = x + (size_t)row * HD;
    float s = 0.f;
    for (int i = threadIdx.x; i < HD; i += 256) s += xr[i];
    red[threadIdx.x] = s; __syncthreads();
    for (int o = 128; o > 0; o >>= 1) {
        if (threadIdx.x < o) red[threadIdx.x] += red[threadIdx.x + o];
        __syncthreads();
    }
    float mu = red[0] * (1.f / HD);
    __syncthreads();
    float v = 0.f;
    for (int i = threadIdx.x; i < HD; i += 256) { float d = xr[i] - mu; v += d * d; }
    red[threadIdx.x] = v; __syncthreads();
    for (int o = 128; o > 0; o >>= 1) {
        if (threadIdx.x < o) red[threadIdx.x] += red[threadIdx.x + o];
        __syncthreads();
    }
    float rstd = rsqrtf(red[0] * (1.f / HD) + 1e-5f);
    __half* yhr = yh + (size_t)row * HD;
    for (int i = threadIdx.x; i < HD; i += 256) {
        float val = (xr[i] - mu) * rstd * g[i] + b[i];
        if (y) y[(size_t)row * HD + i] = val;
        yhr[i] = __float2half(val);
    }
}

// ---------------- QKV projections ----------------
__global__ __launch_bounds__(256) void qkv_mma() {
    extern __shared__ char sm[];
    const __half** Aptr = (const __half**)(sm + HOFF_PTR);
    int tid = threadIdx.x, wid = tid >> 5, lane = tid & 31;
    int g = lane >> 2, tg = lane & 3;
    int warpM = (wid >> 2) * 64, warpN = (wid & 3) * 32;
    const __half* W = blockIdx.z == 0 ? g_wqh : (blockIdx.z == 1 ? g_wkh : g_wvh);
    __half* C = blockIdx.z == 0 ? g_qh : (blockIdx.z == 1 ? g_kh : g_vh);
    int rowBase = blockIdx.y * 128, colBase = blockIdx.x * 128;
    if (tid < 128) Aptr[tid] = g_h1h + (size_t)(rowBase + tid) * HD;
    __syncthreads();
    const __half* Bbase = W + (size_t)colBase * HD;
    uint32_t sb = smem_u32(sm);
    float acc[4][4][4] = {};
    GEMM_MAINLOOP(HD / 32, HD)
#pragma unroll
    for (int mt = 0; mt < 4; mt++)
#pragma unroll
        for (int nt = 0; nt < 4; nt++) {
            int r0 = rowBase + warpM + mt * 16 + g;
            int c0 = colBase + warpN + nt * 8 + 2 * tg;
            *(__half2*)(C + (size_t)r0 * HD + c0) = __floats2half2_rn(acc[mt][nt][0], acc[mt][nt][1]);
            *(__half2*)(C + (size_t)(r0 + 8) * HD + c0) = __floats2half2_rn(acc[mt][nt][2], acc[mt][nt][3]);
        }
}

// ---------------- O projection + residual (writes out only; ln2 reads out) ----------------
__global__ __launch_bounds__(256) void oproj_mma(const float* __restrict__ xres,
                                                 float* __restrict__ out) {
    extern __shared__ char sm[];
    const __half** Aptr = (const __half**)(sm + HOFF_PTR);
    int tid = threadIdx.x, wid = tid >> 5, lane = tid & 31;
    int g = lane >> 2, tg = lane & 3;
    int warpM = (wid >> 2) * 64, warpN = (wid & 3) * 32;
    int rowBase = blockIdx.y * 128, colBase = blockIdx.x * 128;
    if (tid < 128) Aptr[tid] = g_attnh + (size_t)(rowBase + tid) * HD;
    __syncthreads();
    const __half* Bbase = g_woh + (size_t)colBase * HD;
    uint32_t sb = smem_u32(sm);
    float acc[4][4][4] = {};
    GEMM_MAINLOOP(HD / 32, HD)
#pragma unroll
    for (int mt = 0; mt < 4; mt++)
#pragma unroll
        for (int nt = 0; nt < 4; nt++) {
            int r0 = rowBase + warpM + mt * 16 + g;
            int c0 = colBase + warpN + nt * 8 + 2 * tg;
            float2 a = *(const float2*)(xres + (size_t)r0 * HD + c0);
            float2 b = *(const float2*)(xres + (size_t)(r0 + 8) * HD + c0);
            *(float2*)(out + (size_t)r0 * HD + c0) =
                make_float2(acc[mt][nt][0] + a.x, acc[mt][nt][1] + a.y);
            *(float2*)(out + (size_t)(r0 + 8) * HD + c0) =
                make_float2(acc[mt][nt][2] + b.x, acc[mt][nt][3] + b.y);
        }
}

// ---------------- flash attention (causal, fp16 mma) ----------------
#define AQR 128
#define QLD 72
#define VLD 72
#define SM_K (128 * QLD)
#define SM_V (192 * QLD)
#define SMEM_ATTN ((192 * QLD + 64 * VLD) * 2)
__global__ __launch_bounds__(256) void attn_mma() {
    extern __shared__ char sm[];
    __half* Qs = (__half*)sm;
    __half* Ks = (__half*)sm + SM_K;
    __half* Vt = (__half*)sm + SM_V;
    int qb = gridDim.x - 1 - blockIdx.x;
    int bh = blockIdx.y;
    int b = bh >> 4, h = bh & 15;
    int tid = threadIdx.x, wid = tid >> 5, lane = tid & 31;
    int g = lane >> 2, tg = lane & 3;
    int qr0 = wid * 16;
    const __half* qbase = g_qh + (size_t)(b * SEQ + qb * AQR) * HD + h * DH;
#pragma unroll
    for (int i = 0; i < 4; i++) {
        int idx = tid + i * 256;
        int row = idx >> 3, c = (idx & 7) * 8;
        *(uint4*)&Qs[row * QLD + c] = *(const uint4*)(qbase + (size_t)row * HD + c);
    }
    float m0 = -1e30f, m1 = -1e30f, l0 = 0.f, l1 = 0.f;
    float o[8][4] = {};
    int nkt = qb * 2 + 2;
    int rmaxWarp = qb * AQR + qr0 + 15;
    for (int kt = 0; kt < nkt; kt++) {
        __syncthreads();
        const __half* kbase = g_kh + (size_t)(b * SEQ + kt * 64) * HD + h * DH;
        const __half* vbase = g_vh + (size_t)(b * SEQ + kt * 64) * HD + h * DH;
#pragma unroll
        for (int i = 0; i < 2; i++) {
            int idx = tid + i * 256;
            int row = idx >> 3, c = (idx & 7) * 8;
            *(uint4*)&Ks[row * QLD + c] = *(const uint4*)(kbase + (size_t)row * HD + c);
        }
#pragma unroll
        for (int i = 0; i < 8; i++) {
            int idx = tid + i * 256;
            int key = idx & 63, c0 = (idx >> 6) * 2;
            __half2 v = *(const __half2*)(vbase + (size_t)key * HD + c0);
            Vt[(c0 + 0) * VLD + key] = __low2half(v);
            Vt[(c0 + 1) * VLD + key] = __high2half(v);
        }
        __syncthreads();
        if (kt * 64 > rmaxWarp) continue;
        float s[8][4] = {};
#pragma unroll
        for (int c = 0; c < 4; c++) {
            int kk = c * 16 + 4 * tg;
            uint2 aLo = *(const uint2*)&Qs[(qr0 + g) * QLD + kk];
            uint2 aHi = *(const uint2*)&Qs[(qr0 + g + 8) * QLD + kk];
#pragma unroll
            for (int nt = 0; nt < 8; nt++) {
                uint2 bv = *(const uint2*)&Ks[(nt * 8 + g) * QLD + kk];
                mma16(s[nt], aLo.x, aHi.x, aLo.y, aHi.y, bv.x, bv.y);
            }
        }
        int r0 = qb * AQR + qr0 + g, r1 = r0 + 8;
#pragma unroll
        for (int nt = 0; nt < 8; nt++) {
            int c = kt * 64 + nt * 8 + 2 * tg;
            s[nt][0] = (c     > r0) ? -1e30f : s[nt][0] * 0.125f;
            s[nt][1] = (c + 1 > r0) ? -1e30f : s[nt][1] * 0.125f;
            s[nt][2] = (c     > r1) ? -1e30f : s[nt][2] * 0.125f;
            s[nt][3] = (c + 1 > r1) ? -1e30f : s[nt][3] * 0.125f;
        }
        float mx0 = -1e30f, mx1 = -1e30f;
#pragma unroll
        for (int nt = 0; nt < 8; nt++) {
            mx0 = fmaxf(mx0, fmaxf(s[nt][0], s[nt][1]));
            mx1 = fmaxf(mx1, fmaxf(s[nt][2], s[nt][3]));
        }
        mx0 = fmaxf(mx0, __shfl_xor_sync(0xffffffffu, mx0, 1));
        mx0 = fmaxf(mx0, __shfl_xor_sync(0xffffffffu, mx0, 2));
        mx1 = fmaxf(mx1, __shfl_xor_sync(0xffffffffu, mx1, 1));
        mx1 = fmaxf(mx1, __shfl_xor_sync(0xffffffffu, mx1, 2));
        float mn0 = fmaxf(m0, mx0), mn1 = fmaxf(m1, mx1);
        float rs0 = 0.f, rs1 = 0.f;
#pragma unroll
        for (int nt = 0; nt < 8; nt++) {
            s[nt][0] = __expf(s[nt][0] - mn0); rs0 += s[nt][0];
            s[nt][1] = __expf(s[nt][1] - mn0); rs0 += s[nt][1];
            s[nt][2] = __expf(s[nt][2] - mn1); rs1 += s[nt][2];
            s[nt][3] = __expf(s[nt][3] - mn1); rs1 += s[nt][3];
        }
        rs0 += __shfl_xor_sync(0xffffffffu, rs0, 1);
        rs0 += __shfl_xor_sync(0xffffffffu, rs0, 2);
        rs1 += __shfl_xor_sync(0xffffffffu, rs1, 1);
        rs1 += __shfl_xor_sync(0xffffffffu, rs1, 2);
        float al0 = __expf(m0 - mn0), al1 = __expf(m1 - mn1);
        m0 = mn0; m1 = mn1;
        l0 = l0 * al0 + rs0; l1 = l1 * al1 + rs1;
#pragma unroll
        for (int nt = 0; nt < 8; nt++) {
            o[nt][0] *= al0; o[nt][1] *= al0;
            o[nt][2] *= al1; o[nt][3] *= al1;
        }
#pragma unroll
        for (int j = 0; j < 4; j++) {
            uint32_t a0 = pack2(s[2 * j][0], s[2 * j][1]);
            uint32_t a1 = pack2(s[2 * j][2], s[2 * j][3]);
            uint32_t a2 = pack2(s[2 * j + 1][0], s[2 * j + 1][1]);
            uint32_t a3 = pack2(s[2 * j + 1][2], s[2 * j + 1][3]);
            int kbase2 = j * 16 + 2 * tg;
#pragma unroll
            for (int nt = 0; nt < 8; nt++) {
                const __half* vp = &Vt[(nt * 8 + g) * VLD];
                uint32_t b0 = *(const uint32_t*)(vp + kbase2);
                uint32_t b1 = *(const uint32_t*)(vp + kbase2 + 8);
                mma16(o[nt], a0, a1, a2, a3, b0, b1);
            }
        }
    }
    float i0 = 1.f / l0, i1 = 1.f / l1;
    __half* obase = g_attnh + (size_t)(b * SEQ + qb * AQR + qr0) * HD + h * DH;
#pragma unroll
    for (int nt = 0; nt < 8; nt++) {
        int c = nt * 8 + 2 * tg;
        *(__half2*)(obase + (size_t)g * HD + c)       = __floats2half2_rn(o[nt][0] * i0, o[nt][1] * i0);
        *(__half2*)(obase + (size_t)(g + 8) * HD + c) = __floats2half2_rn(o[nt][2] * i1, o[nt][3] * i1);
    }
}

// ---------------- router (fp32 logits) ----------------
__global__ void router_kernel(const float* __restrict__ Wr) {
    int gwarp = (blockIdx.x * blockDim.x + threadIdx.x) >> 5;
    int lane = threadIdx.x & 31;
    if (gwarp >= TOK) return;
    const float* xr = g_h2 + (size_t)gwarp * HD;
    float acc[NEXP] = {};
    for (int i = lane; i < HD; i += 32) {
        float xv = xr[i];
#pragma unroll
        for (int e = 0; e < NEXP; e++) acc[e] += xv * Wr[e * HD + i];
    }
#pragma unroll
    for (int e = 0; e < NEXP; e++)
#pragma unroll
        for (int o = 16; o > 0; o >>= 1)
            acc[e] += __shfl_xor_sync(0xffffffffu, acc[e], o);
    if (lane == 0) {
        float mx = acc[0];
#pragma unroll
        for (int e = 1; e < NEXP; e++) mx = fmaxf(mx, acc[e]);
        float p[NEXP], se = 0.f;
#pragma unroll
        for (int e = 0; e < NEXP; e++) { p[e] = __expf(acc[e] - mx); se += p[e]; }
        float inv = 1.f / (se * (float)TOK);
#pragma unroll
        for (int e = 0; e < NEXP; e++) atomicAdd(&g_usage[e], p[e] * inv);
        int i0 = 0;
#pragma unroll
        for (int e = 1; e < NEXP; e++) if (acc[e] > acc[i0]) i0 = e;
        int i1 = (i0 == 0) ? 1 : 0;
#pragma unroll
        for (int e = 0; e < NEXP; e++) if (e != i0 && acc[e] > acc[i1]) i1 = e;
        float l0 = acc[i0], l1 = acc[i1];
        float m2 = fmaxf(l0, l1);
        float e0 = __expf(l0 - m2), e1 = __expf(l1 - m2);
        float s2 = e0 + e1;
        g_we[gwarp * NEXP + i0] = e0 / s2;
        g_we[gwarp * NEXP + i1] = e1 / s2;
        int p0 = atomicAdd(&g_cnt[i0], 1); g_idx[i0 * TOK + p0] = gwarp;
        int p1 = atomicAdd(&g_cnt[i1], 1); g_idx[i1 * TOK + p1] = gwarp;
    }
}

// ---------------- MoE up (fp16) ----------------
__global__ __launch_bounds__(256) void moe_up_mma() {
    extern __shared__ char sm[];
    int e = blockIdx.z;
    int cnt = g_cnt[e];
    int rowBase = blockIdx.y * 128;
    if (rowBase >= cnt) return;
    int half_ = blockIdx.x >> 5;
    int colBase = (blockIdx.x & 31) * 128;
    const __half* W = half_ ? g_w3h : g_w1h;
    __half* dstb = half_ ? g_hgB : g_hgA;
    const __half** Aptr = (const __half**)(sm + HOFF_PTR);
    int tid = threadIdx.x, wid = tid >> 5, lane = tid & 31;
    int g = lane >> 2, tg = lane & 3;
    int warpM = (wid >> 2) * 64, warpN = (wid & 3) * 32;
    if (tid < 128) {
        int p = rowBase + tid;
        Aptr[tid] = g_h2h + (size_t)g_idx[e * TOK + (p < cnt ? p : cnt - 1)] * HD;
    }
    __syncthreads();
    const __half* Bbase = W + (size_t)e * FF * HD + (size_t)colBase * HD;
    uint32_t sb = smem_u32(sm);
    float acc[4][4][4] = {};
    GEMM_MAINLOOP(HD / 32, HD)
#pragma unroll
    for (int mt = 0; mt < 4; mt++)
#pragma unroll
        for (int nt = 0; nt < 4; nt++) {
            int p0 = rowBase + warpM + mt * 16 + g;
            int c0 = colBase + warpN + nt * 8 + 2 * tg;
            if (p0 < cnt)
                *(__half2*)(dstb + ((size_t)e * TOK + p0) * FF + c0) =
                    __floats2half2_rn(acc[mt][nt][0], acc[mt][nt][1]);
            if (p0 + 8 < cnt)
                *(__half2*)(dstb + ((size_t)e * TOK + p0 + 8) * FF + c0) =
                    __floats2half2_rn(acc[mt][nt][2], acc[mt][nt][3]);
        }
}

// ---------------- silu * mul (half) ----------------
__global__ void silu_mul_kernel() {
    int e = blockIdx.y;
    int cnt = g_cnt[e];
    int pos = blockIdx.x;
    if (pos >= cnt) return;
    size_t off2 = ((size_t)e * TOK + pos) * (FF / 2);
    __half2* A2 = (__half2*)g_hgA;
    const __half2* B2 = (const __half2*)g_hgB;
    for (int i = threadIdx.x; i < FF / 2; i += 256) {
        float2 a = __half22float2(A2[off2 + i]);
        float2 b = __half22float2(B2[off2 + i]);
        a.x = a.x / (1.f + __expf(-a.x)) * b.x;
        a.y = a.y / (1.f + __expf(-a.y)) * b.y;
        A2[off2 + i] = __floats2half2_rn(a.x, a.y);
    }
}

// ---------------- MoE down (fp16, scatter-atomic) ----------------
__global__ __launch_bounds__(256) void moe_down_mma(float* __restrict__ out) {
    extern __shared__ char sm[];
    int e = blockIdx.z;
    int cnt = g_cnt[e];
    int rowBase = blockIdx.y * 128;
    if (rowBase >= cnt) return;
    int colBase = blockIdx.x * 128;
    const __half** Aptr = (const __half**)(sm + HOFF_PTR);
    int tid = threadIdx.x, wid = tid >> 5, lane = tid & 31;
    int g = lane >> 2, tg = lane & 3;
    int warpM = (wid >> 2) * 64, warpN = (wid & 3) * 32;
    if (tid < 128)
        Aptr[tid] = g_hgA + ((size_t)e * TOK + rowBase + tid) * FF;
    __syncthreads();
    const __half* Bbase = g_w2h + (size_t)e * HD * FF + (size_t)colBase * FF;
    uint32_t sb = smem_u32(sm);
    float acc[4][4][4] = {};
    GEMM_MAINLOOP(FF / 32, FF)
#pragma unroll
    for (int mt = 0; mt < 4; mt++) {
        int p0 = rowBase + warpM + mt * 16 + g;
        int p1 = p0 + 8;
        int t0 = 0, t1 = 0; float w0 = 0.f, w1 = 0.f;
        if (p0 < cnt) { t0 = g_idx[e * TOK + p0]; w0 = g_we[t0 * NEXP + e]; }
        if (p1 < cnt) { t1 = g_idx[e * TOK + p1]; w1 = g_we[t1 * NEXP + e]; }
#pragma unroll
        for (int nt = 0; nt < 4; nt++) {
            int c0 = colBase + warpN + nt * 8 + 2 * tg;
            if (p0 < cnt) {
                atomicAdd(out + (size_t)t0 * HD + c0,     w0 * acc[mt][nt][0]);
                atomicAdd(out + (size_t)t0 * HD + c0 + 1, w0 * acc[mt][nt][1]);
            }
            if (p1 < cnt) {
                atomicAdd(out + (size_t)t1 * HD + c0,     w1 * acc[mt][nt][2]);
                atomicAdd(out + (size_t)t1 * HD + c0 + 1, w1 * acc[mt][nt][3]);
            }
        }
    }
}

// ---------------- lb ----------------
__global__ void lb_kernel(float* __restrict__ out) {
    if (threadIdx.x == 0) {
        float s = 0.f;
#pragma unroll
        for (int e = 0; e < NEXP; e++) s += g_usage[e] * g_usage[e];
        out[(size_t)TOK * HD] = (float)NEXP * s;
    }
}

// ---------------- launch ----------------
extern "C" void kernel_launch(void* const* d_in, const int* in_sizes, int n_in,
                              void* d_out, int out_size) {
    const float* x    = (const float*)d_in[0];
    const float* Wq   = (const float*)d_in[1];
    const float* Wk   = (const float*)d_in[2];
    const float* Wv   = (const float*)d_in[3];
    const float* Wo   = (const float*)d_in[4];
    const float* ln1g = (const float*)d_in[5];
    const float* ln1b = (const float*)d_in[6];
    const float* ln2g = (const float*)d_in[7];
    const float* ln2b = (const float*)d_in[8];
    const float* Wr   = (const float*)d_in[9];
    const float* W1   = (const float*)d_in[10];
    const float* W2   = (const float*)d_in[11];
    const float* W3   = (const float*)d_in[12];
    float* out = (float*)d_out;

    float *ph2;
    __half *ph1h, *ph2h;
    cudaGetSymbolAddress((void**)&ph1h, g_h1h);
    cudaGetSymbolAddress((void**)&ph2,  g_h2);
    cudaGetSymbolAddress((void**)&ph2h, g_h2h);

    cudaFuncSetAttribute(qkv_mma,      cudaFuncAttributeMaxDynamicSharedMemorySize, SMEM_GEMMH);
    cudaFuncSetAttribute(oproj_mma,    cudaFuncAttributeMaxDynamicSharedMemorySize, SMEM_GEMMH);
    cudaFuncSetAttribute(moe_up_mma,   cudaFuncAttributeMaxDynamicSharedMemorySize, SMEM_GEMMH);
    cudaFuncSetAttribute(moe_down_mma, cudaFuncAttributeMaxDynamicSharedMemorySize, SMEM_GEMMH);
    cudaFuncSetAttribute(attn_mma,     cudaFuncAttributeMaxDynamicSharedMemorySize, SMEM_ATTN);

    cudaStream_t s2;
    cudaEvent_t evFork, evJoin;
    cudaStreamCreateWithFlags(&s2, cudaStreamNonBlocking);
    cudaEventCreateWithFlags(&evFork, cudaEventDisableTiming);
    cudaEventCreateWithFlags(&evJoin, cudaEventDisableTiming);

    const int NQ4 = HD * HD / 4;
    const int NW4 = NEXP * FF * HD / 4;

    cudaEventRecord(evFork, 0);
    cudaStreamWaitEvent(s2, evFork, 0);
    cvt3_kernel<<<dim3((NW4 + 255) / 256, 3), 256, 0, s2>>>(W1, W2, W3, NW4);
    cudaEventRecord(evJoin, s2);

    init_kernel<<<1, 32>>>();
    cvt4_kernel<<<dim3((NQ4 + 255) / 256, 4), 256>>>(Wq, Wk, Wv, Wo, NQ4);
    ln_kernel<<<TOK, 256>>>(x, ln1g, ln1b, nullptr, ph1h);
    qkv_mma<<<dim3(HD / 128, TOK / 128, 3), 256, SMEM_GEMMH>>>();
    attn_mma<<<dim3(SEQ / AQR, 2 * NHEAD), 256, SMEM_ATTN>>>();
    oproj_mma<<<dim3(HD / 128, TOK / 128), 256, SMEM_GEMMH>>>(x, out);
    ln_kernel<<<TOK, 256>>>(out, ln2g, ln2b, ph2, ph2h);
    router_kernel<<<TOK / 8, 256>>>(Wr);

    cudaStreamWaitEvent(0, evJoin, 0);
    moe_up_mma<<<dim3(2 * FF / 128, TOK / 128, NEXP), 256, SMEM_GEMMH>>>();
    silu_mul_kernel<<<dim3(TOK, NEXP), 256>>>();
    moe_down_mma<<<dim3(HD / 128, TOK / 128, NEXP), 256, SMEM_GEMMH>>>(out);
    if ((long long)out_size >= (long long)TOK * HD + 1)
        lb_kernel<<<1, 32>>>(out);
}